// round 9
// baseline (speedup 1.0000x reference)
#include <cuda_runtime.h>
#include <cstdint>

#define B  8
#define N  4096
#define F  128
#define GS 1024

#define RPC 4                        // rows per gather CTA
#define GATHER_SMEM (RPC * N * 4 + GS * 4)   // 4x16KB rows + 4KB idx = 69632B

// Scratch
__device__ unsigned int       g_keys[B * N];   // monotone-mapped values
__device__ unsigned int       g_hist[B * 256]; // top-8-bit histogram (re-zeroed by select)
__device__ unsigned long long g_sel[B * GS];   // selected composites, unordered
__device__ int                g_idx[B * GS];   // final top-k indices, jax order

__device__ __forceinline__ unsigned int monot(float v) {
    unsigned int u = __float_as_uint(v);
    return (u & 0x80000000u) ? ~u : (u | 0x80000000u); // bigger float -> bigger uint
}

// ---------------------------------------------------------------------------
// K1: chip-wide extract + per-batch 256-bin histogram of the top 8 key bits.
// ---------------------------------------------------------------------------
__global__ __launch_bounds__(256) void extract_hist_kernel(const float* __restrict__ x)
{
    __shared__ unsigned int h[256];
    const int tid = threadIdx.x;
    h[tid] = 0;
    __syncthreads();

    const int i = blockIdx.x * 256 + tid;   // 0 .. B*N-1
    const int b = i >> 12;
    unsigned int u = monot(__ldcs(&x[(size_t)i * F + (F - 1)]));
    g_keys[i] = u;
    atomicAdd(&h[u >> 24], 1u);
    __syncthreads();

    unsigned int c = h[tid];
    if (c) atomicAdd(&g_hist[b * 256 + tid], c);
}

// ---------------------------------------------------------------------------
// K2: per-batch threshold + compaction (cheap).
// composite = (u << 12) | (4095 - i): larger == earlier in jax order.
// ---------------------------------------------------------------------------
__device__ __forceinline__ void scan_hist(const unsigned int* hist, unsigned int need,
                                          unsigned int* s_bin, unsigned int* s_above)
{
    const int tid = threadIdx.x;
    if (tid < 32) {
        unsigned int sum = 0;
        #pragma unroll
        for (int j = 0; j < 8; ++j) sum += hist[tid * 8 + j];
        unsigned int acc = sum;
        #pragma unroll
        for (int off = 1; off < 32; off <<= 1) {
            unsigned int t = __shfl_down_sync(0xFFFFFFFFu, acc, off);
            if (tid + off < 32) acc += t;
        }
        unsigned int running = acc - sum;      // strictly above my 8-bin group
        #pragma unroll
        for (int j = 7; j >= 0; --j) {
            unsigned int c = hist[tid * 8 + j];
            if (running < need && need <= running + c) {
                *s_bin = (unsigned int)(tid * 8 + j);
                *s_above = running;
            }
            running += c;
        }
    }
}

__global__ __launch_bounds__(1024) void select_kernel()
{
    __shared__ unsigned long long cand[N];      // 32 KB
    __shared__ unsigned int hist[256];
    __shared__ unsigned int s_bin, s_above, s_m, s_cnt;

    const int b   = blockIdx.x;
    const int tid = threadIdx.x;

    if (tid < 256) { hist[tid] = g_hist[b * 256 + tid]; g_hist[b * 256 + tid] = 0; }
    if (tid == 0) { s_m = 0; s_cnt = 0; }
    __syncthreads();

    scan_hist(hist, GS, &s_bin, &s_above);
    __syncthreads();
    const unsigned int bin1 = s_bin;
    unsigned int need = GS - s_above;

    unsigned long long comp[4];
    #pragma unroll
    for (int l = 0; l < 4; ++l) {
        int i = l * 1024 + tid;
        unsigned int u = g_keys[b * N + i];
        comp[l] = ((unsigned long long)u << 12) | (unsigned int)(N - 1 - i);
        if ((u >> 24) == bin1) {
            unsigned int p = atomicAdd(&s_m, 1u);
            cand[p] = comp[l];
        }
    }
    __syncthreads();
    const unsigned int m = s_m;

    unsigned long long prefix = (unsigned long long)bin1 << 36;
    unsigned long long pmask  = 0xFFull << 36;

    #pragma unroll
    for (int pass = 0; pass < 5; ++pass) {
        const int          shift = (pass < 4) ? (28 - 8 * pass) : 0;
        const unsigned int dmask = (pass < 4) ? 0xFFu : 0xFu;

        if (tid < 256) hist[tid] = 0;
        __syncthreads();
        for (unsigned int idx = tid; idx < m; idx += 1024) {
            unsigned long long k = cand[idx];
            if ((k & pmask) == prefix)
                atomicAdd(&hist[(unsigned int)(k >> shift) & dmask], 1u);
        }
        __syncthreads();
        scan_hist(hist, need, &s_bin, &s_above);
        __syncthreads();
        prefix |= ((unsigned long long)s_bin) << shift;
        pmask  |= ((unsigned long long)dmask) << shift;
        need   -= s_above;
        __syncthreads();
    }
    // prefix == exact GS-th largest composite. Selected: composite >= prefix.

    #pragma unroll
    for (int l = 0; l < 4; ++l) {
        if (comp[l] >= prefix) {
            unsigned int p = atomicAdd(&s_cnt, 1u);
            g_sel[b * GS + p] = comp[l];
        }
    }
}

// ---------------------------------------------------------------------------
// K3: rank-by-count over 1024 selected keys, 64 CTAs x 128 thr.
// ---------------------------------------------------------------------------
__global__ __launch_bounds__(128) void rank_kernel()
{
    __shared__ unsigned long long sk[GS];  // 8 KB

    const int b   = blockIdx.x >> 3;
    const int c   = blockIdx.x & 7;
    const int tid = threadIdx.x;

    #pragma unroll
    for (int l = 0; l < GS / 128; ++l)
        sk[tid + l * 128] = g_sel[b * GS + tid + l * 128];
    __syncthreads();

    const unsigned long long mine = sk[c * 128 + tid];
    int rank = 0;
    #pragma unroll 8
    for (int j = 0; j < GS; ++j)
        rank += (sk[j] > mine);

    g_idx[b * GS + rank] = (N - 1) - (int)(mine & 0xFFFull);
}

// ---------------------------------------------------------------------------
// K4: gather, RPC=4 rows per CTA. All 4 row loads issued back-to-back
// (32 LDG.128 in flight per thread), ONE sync, then 4 smem gathers.
// sidx loaded once per 4 rows (1/4 the index L2 traffic of 1-row CTAs).
// ---------------------------------------------------------------------------
__global__ __launch_bounds__(512) void gather_kernel(const float* __restrict__ A,
                                                     const float* __restrict__ x,
                                                     float* __restrict__ out)
{
    extern __shared__ float smem[];
    float* bufs = smem;                   // RPC x 4096 floats
    int*   sidx = (int*)(smem + RPC * N); // 1024 ints

    const int bi  = blockIdx.x;            // 0 .. B*GS/RPC-1
    const int b   = bi >> 8;                // 256 CTAs per batch
    const int i0  = (bi & 255) * RPC;
    const int tid = threadIdx.x;

    const int* gi = g_idx + b * GS;

    // Row indices for my 4 rows (direct global reads, no sync needed)
    int ri[RPC];
    #pragma unroll
    for (int r = 0; r < RPC; ++r) ri[r] = __ldg(&gi[i0 + r]);

    // Issue all 4 row loads (streaming) into 4 smem buffers
    #pragma unroll
    for (int r = 0; r < RPC; ++r) {
        const float4* arow = (const float4*)(A + ((size_t)b * N + ri[r]) * N);
        float4* rowv = (float4*)(bufs + r * N);
        rowv[tid]       = __ldcs(&arow[tid]);
        rowv[tid + 512] = __ldcs(&arow[tid + 512]);
    }

    // Column indices (1024 ints, 2 per thread)
    sidx[tid]       = gi[tid];
    sidx[tid + 512] = gi[tid + 512];

    // xg rows: 4 rows x 32 float4 = threads 0..127
    if (tid < RPC * (F / 4)) {
        const int r    = tid >> 5;
        const int lane = tid & 31;
        const float4* xrow = (const float4*)(x + ((size_t)b * N + ri[r]) * F);
        float4* xgrow = (float4*)(out + (size_t)B * GS * GS
                                      + ((size_t)b * GS + i0 + r) * F);
        xgrow[lane] = __ldcs(&xrow[lane]);
    }

    __syncthreads();

    // Gather all 4 rows
    #pragma unroll
    for (int r = 0; r < RPC; ++r) {
        const float* buf = bufs + r * N;
        float* orow = out + ((size_t)b * GS + i0 + r) * GS;
        orow[tid]       = buf[sidx[tid]];
        orow[tid + 512] = buf[sidx[tid + 512]];
    }
}

// ---------------------------------------------------------------------------
extern "C" void kernel_launch(void* const* d_in, const int* in_sizes, int n_in,
                              void* d_out, int out_size)
{
    const float* A = (const float*)d_in[0];  // (8,4096,4096) f32
    const float* x = (const float*)d_in[1];  // (8,4096,128)  f32
    float* out = (float*)d_out;              // At2 (8,1024,1024) ++ xg (8,1024,128)

    cudaFuncSetAttribute(gather_kernel,
                         cudaFuncAttributeMaxDynamicSharedMemorySize, GATHER_SMEM);

    extract_hist_kernel<<<(B * N) / 256, 256>>>(x);
    select_kernel<<<B, 1024>>>();
    rank_kernel<<<B * 8, 128>>>();
    gather_kernel<<<B * GS / RPC, 512, GATHER_SMEM>>>(A, x, out);
}